// round 8
// baseline (speedup 1.0000x reference)
#include <cuda_runtime.h>
#include <cstdint>

// Problem constants
constexpr int R     = 128;   // rank (i, k)
constexpr int D     = 128;   // input dim (j)
constexpr int M_OUT = 32;    // output dim
constexpr int NB    = 128;   // batch N
constexpr int L     = 512;   // sequence length

// Time-chunking: scratch must stay far below the aarch64 ±4GB .bss
// relocation limit. 128 steps * 128 n * 128 i * 128 k * 4B = 1.07 GB.
constexpr int CHUNK_T = 128;
constexpr int NCHUNKS = L / CHUNK_T;    // 4

constexpr size_t G_ELEMS = (size_t)CHUNK_T * NB * R * R;
__device__ float g_G[G_ELEMS];          // G[t_local][n][i][k]
__device__ float g_h[NB * R];           // carried hidden state between chunks

// ---------------------------------------------------------------------------
// Phase 1 (per chunk): G[(t,n),(i,k)] = X[(t,n), j] @ Aflat[j, (i,k)]
// CTA = (i block = all 128 k for one i, t_local). Rows of the tile are n.
// BM=128(n), BN=128(k), BK=16(j), 256 threads, 8x8 microtile, FFMA2.
// ---------------------------------------------------------------------------
__global__ __launch_bounds__(256, 2) void compute_G_kernel(
    const float* __restrict__ X,   // [N][L][D]
    const float* __restrict__ A,   // [R][D][R]
    int chunk_base)                // first global t of this chunk
{
    const int ib  = blockIdx.x;            // i value
    const int tl  = blockIdx.y;            // local t within chunk
    const int t   = chunk_base + tl;       // global t
    const int tid = threadIdx.x;

    __shared__ float Xs[16][128];  // [j][n]  transposed x tile
    __shared__ float Bs[16][128];  // [j][k]  A[ib] slab tile

    const float* Aslab = A + (size_t)ib * (D * R);   // contiguous [j][k], 64KB

    const int tx = tid & 15;       // k microtile: cols tx*8 .. +7
    const int ty = tid >> 4;       // n microtile: rows ty*8 .. +7

    alignas(16) unsigned long long c2[8][4];   // 8 rows x 4 f32x2 = 8x8 fp32
    #pragma unroll
    for (int m = 0; m < 8; ++m)
        #pragma unroll
        for (int p = 0; p < 4; ++p) c2[m][p] = 0ull;

    const int xrow = tid & 127;    // n
    const int c4b  = tid >> 7;     // which float4 of the 16-wide j tile

    for (int jt = 0; jt < D; jt += 16) {
        // X tile, transposed into Xs[j][n] (bank = n%32 -> conflict-free STS)
        #pragma unroll
        for (int l = 0; l < 2; ++l) {
            const int c4 = c4b + l * 2;
            const float4 v = *reinterpret_cast<const float4*>(
                X + ((size_t)xrow * L + t) * D + jt + c4 * 4);
            Xs[c4 * 4 + 0][xrow] = v.x;
            Xs[c4 * 4 + 1][xrow] = v.y;
            Xs[c4 * 4 + 2][xrow] = v.z;
            Xs[c4 * 4 + 3][xrow] = v.w;
        }
        // A slab tile (already [j][k] row-major; fully coalesced)
        #pragma unroll
        for (int l = 0; l < 2; ++l) {
            const int lin = tid + l * 256;
            const int j   = lin >> 5;
            const int k4  = lin & 31;
            *reinterpret_cast<float4*>(&Bs[j][k4 * 4]) =
                *reinterpret_cast<const float4*>(Aslab + (size_t)(jt + j) * R + k4 * 4);
        }
        __syncthreads();

        #pragma unroll
        for (int j = 0; j < 16; ++j) {
            float a[8];
            *reinterpret_cast<float4*>(&a[0]) =
                *reinterpret_cast<const float4*>(&Xs[j][ty * 8]);
            *reinterpret_cast<float4*>(&a[4]) =
                *reinterpret_cast<const float4*>(&Xs[j][ty * 8 + 4]);

            unsigned long long b2[4];
            const unsigned long long* bp =
                reinterpret_cast<const unsigned long long*>(&Bs[j][tx * 8]);
            b2[0] = bp[0]; b2[1] = bp[1]; b2[2] = bp[2]; b2[3] = bp[3];

            #pragma unroll
            for (int m = 0; m < 8; ++m) {
                unsigned long long a2;
                const unsigned int au = __float_as_uint(a[m]);
                asm("mov.b64 %0, {%1, %1};" : "=l"(a2) : "r"(au));
                #pragma unroll
                for (int p = 0; p < 4; ++p) {
                    asm("fma.rn.f32x2 %0, %1, %2, %0;"
                        : "+l"(c2[m][p]) : "l"(a2), "l"(b2[p]));
                }
            }
        }
        __syncthreads();
    }

    // Epilogue: write 8x8 microtile to G[tl][n][ib][k]
    #pragma unroll
    for (int m = 0; m < 8; ++m) {
        const int n = ty * 8 + m;
        float* dst = g_G + ((size_t)tl * NB + n) * ((size_t)R * R)
                         + (size_t)ib * R + tx * 8;
        const float4* src = reinterpret_cast<const float4*>(&c2[m][0]);
        *reinterpret_cast<float4*>(dst)     = src[0];
        *reinterpret_cast<float4*>(dst + 4) = src[1];
    }
}

// ---------------------------------------------------------------------------
// Phase 2 (per chunk): sequential scan, one CTA per sequence n.
// h starts as alpha on the first chunk (h0 = step formula applied to alpha),
// carries through g_h between chunks, last chunk applies Omega.
// Per step: h_new[k] = sum_i h[i] * G[tl][n][i][k]  (loads h-independent).
// ---------------------------------------------------------------------------
__global__ __launch_bounds__(128) void scan_kernel(
    const float* __restrict__ alpha,   // [R]
    const float* __restrict__ Omega,   // [R][M_OUT]
    float* __restrict__ out,           // [N][M_OUT]
    int is_first, int is_last)
{
    const int n   = blockIdx.x;
    const int tid = threadIdx.x;
    const int w   = tid >> 5;   // warp id 0..3 -> i residue class
    const int l   = tid & 31;   // lane -> k = 4*l .. 4*l+3

    __shared__ float h[128];
    __shared__ float part[4][128];

    h[tid] = is_first ? alpha[tid] : g_h[n * R + tid];
    __syncthreads();

    for (int tl = 0; tl < CHUNK_T; ++tl) {
        const float* Gt = g_G + ((size_t)tl * NB + n) * ((size_t)R * R);
        float4 acc = make_float4(0.f, 0.f, 0.f, 0.f);
        #pragma unroll
        for (int ii = 0; ii < 32; ++ii) {
            const int i = w + ii * 4;
            const float hv = h[i];                          // smem broadcast
            const float4 g4 = *reinterpret_cast<const float4*>(
                Gt + (size_t)i * R + l * 4);                // coalesced LDG.128
            acc.x = fmaf(hv, g4.x, acc.x);
            acc.y = fmaf(hv, g4.y, acc.y);
            acc.z = fmaf(hv, g4.z, acc.z);
            acc.w = fmaf(hv, g4.w, acc.w);
        }
        *reinterpret_cast<float4*>(&part[w][l * 4]) = acc;
        __syncthreads();
        h[tid] = part[0][tid] + part[1][tid] + part[2][tid] + part[3][tid];
        __syncthreads();
    }

    if (is_last) {
        if (tid < M_OUT) {
            float s = 0.f;
            #pragma unroll 4
            for (int k = 0; k < R; ++k)
                s = fmaf(h[k], Omega[k * M_OUT + tid], s);
            out[n * M_OUT + tid] = s;
        }
    } else {
        g_h[n * R + tid] = h[tid];
    }
}

// ---------------------------------------------------------------------------
// Launch: 2 kernels per chunk, serialized on the capture stream.
// Inputs (metadata order): x [N*L*D], alpha [R], A [R*D*R], Omega [R*M_OUT]
// Output: float32 [N, M_OUT]
// ---------------------------------------------------------------------------
extern "C" void kernel_launch(void* const* d_in, const int* in_sizes, int n_in,
                              void* d_out, int out_size)
{
    (void)in_sizes; (void)n_in; (void)out_size;
    const float* x     = (const float*)d_in[0];
    const float* alpha = (const float*)d_in[1];
    const float* A     = (const float*)d_in[2];
    const float* Omega = (const float*)d_in[3];
    float* out = (float*)d_out;

    for (int c = 0; c < NCHUNKS; ++c) {
        dim3 grid1(R, CHUNK_T);            // 128 i-blocks x 128 local steps
        compute_G_kernel<<<grid1, 256>>>(x, A, c * CHUNK_T);
        scan_kernel<<<NB, 128>>>(alpha, Omega, out,
                                 c == 0 ? 1 : 0,
                                 c == NCHUNKS - 1 ? 1 : 0);
    }
}

// round 9
// speedup vs baseline: 1.4319x; 1.4319x over previous
#include <cuda_runtime.h>
#include <cstdint>

// Problem constants
constexpr int R     = 128;   // rank (i, k)
constexpr int D     = 128;   // input dim (j)
constexpr int M_OUT = 32;    // output dim
constexpr int NB    = 128;   // batch N
constexpr int L     = 512;   // sequence length

// Time-chunking keeps .bss ~1GB (aarch64 ±4GB relocation limit).
constexpr int CHUNK_T = 128;
constexpr int NCHUNKS = L / CHUNK_T;    // 4

constexpr size_t G_ELEMS = (size_t)CHUNK_T * NB * R * R;
__device__ float g_G[G_ELEMS];          // G[t_local][n][i][k]
__device__ float g_h[NB * R];           // carried hidden state between chunks

// ---------------------------------------------------------------------------
// Phase 1 (per chunk): G[(t,n),(i,k)] = X[(t,n), j] @ A[i][j][k]
// CTA = (i, t_local). BM=128(n), BN=128(k), BK=16(j), 256 thr, 8x8 microtile,
// FFMA2 inner product, 2-stage smem double buffering (1 bar / BK iter).
// ---------------------------------------------------------------------------
__global__ __launch_bounds__(256, 2) void compute_G_kernel(
    const float* __restrict__ X,   // [N][L][D]
    const float* __restrict__ A,   // [R][D][R]
    int chunk_base)
{
    const int ib  = blockIdx.x;            // i value
    const int tl  = blockIdx.y;            // local t
    const int t   = chunk_base + tl;       // global t
    const int tid = threadIdx.x;

    __shared__ float Xs[2][16][128];       // [buf][j][n]
    __shared__ float Bs[2][16][128];       // [buf][j][k]

    const float* Aslab = A + (size_t)ib * (D * R);   // [j][k] contiguous, 64KB

    const int tx   = tid & 15;     // k microtile: cols tx*8..+7
    const int ty   = tid >> 4;     // n microtile: rows ty*8..+7
    const int xrow = tid & 127;    // n for X loads
    const int c4b  = tid >> 7;     // float4 slot within 16-wide j tile

    alignas(16) unsigned long long c2[8][4];
    #pragma unroll
    for (int m = 0; m < 8; ++m)
        #pragma unroll
        for (int p = 0; p < 4; ++p) c2[m][p] = 0ull;

    float4 xr[2], br[2];

    auto LDG_TILE = [&](int jt) {
        #pragma unroll
        for (int q = 0; q < 2; ++q) {
            const int c4 = c4b + 2 * q;
            xr[q] = *reinterpret_cast<const float4*>(
                X + ((size_t)xrow * L + t) * D + jt + c4 * 4);
        }
        #pragma unroll
        for (int q = 0; q < 2; ++q) {
            const int lin = tid + 256 * q;
            const int j   = lin >> 5;
            const int k4  = lin & 31;
            br[q] = *reinterpret_cast<const float4*>(
                Aslab + (size_t)(jt + j) * R + k4 * 4);
        }
    };
    auto STS_TILE = [&](int buf) {
        #pragma unroll
        for (int q = 0; q < 2; ++q) {
            const int c4 = c4b + 2 * q;
            Xs[buf][c4 * 4 + 0][xrow] = xr[q].x;
            Xs[buf][c4 * 4 + 1][xrow] = xr[q].y;
            Xs[buf][c4 * 4 + 2][xrow] = xr[q].z;
            Xs[buf][c4 * 4 + 3][xrow] = xr[q].w;
        }
        #pragma unroll
        for (int q = 0; q < 2; ++q) {
            const int lin = tid + 256 * q;
            const int j   = lin >> 5;
            const int k4  = lin & 31;
            *reinterpret_cast<float4*>(&Bs[buf][j][k4 * 4]) = br[q];
        }
    };

    LDG_TILE(0);
    STS_TILE(0);
    __syncthreads();

    #pragma unroll
    for (int it = 0; it < 8; ++it) {
        const int p = it & 1;
        if (it < 7) LDG_TILE((it + 1) * 16);   // hide LDG under compute

        #pragma unroll
        for (int j = 0; j < 16; ++j) {
            float a[8];
            *reinterpret_cast<float4*>(&a[0]) =
                *reinterpret_cast<const float4*>(&Xs[p][j][ty * 8]);
            *reinterpret_cast<float4*>(&a[4]) =
                *reinterpret_cast<const float4*>(&Xs[p][j][ty * 8 + 4]);

            unsigned long long b2[4];
            const unsigned long long* bp =
                reinterpret_cast<const unsigned long long*>(&Bs[p][j][tx * 8]);
            b2[0] = bp[0]; b2[1] = bp[1]; b2[2] = bp[2]; b2[3] = bp[3];

            #pragma unroll
            for (int m = 0; m < 8; ++m) {
                unsigned long long a2;
                const unsigned int au = __float_as_uint(a[m]);
                asm("mov.b64 %0, {%1, %1};" : "=l"(a2) : "r"(au));
                #pragma unroll
                for (int q = 0; q < 4; ++q) {
                    asm("fma.rn.f32x2 %0, %1, %2, %0;"
                        : "+l"(c2[m][q]) : "l"(a2), "l"(b2[q]));
                }
            }
        }

        if (it < 7) {
            STS_TILE(1 - p);       // safe: other buffer, bar follows
            __syncthreads();
        }
    }

    // Epilogue: 8x8 microtile -> G[tl][n][ib][k]
    #pragma unroll
    for (int m = 0; m < 8; ++m) {
        const int n = ty * 8 + m;
        float* dst = g_G + ((size_t)tl * NB + n) * ((size_t)R * R)
                         + (size_t)ib * R + tx * 8;
        const float4* src = reinterpret_cast<const float4*>(&c2[m][0]);
        *reinterpret_cast<float4*>(dst)     = src[0];
        *reinterpret_cast<float4*>(dst + 4) = src[1];
    }
}

// ---------------------------------------------------------------------------
// Phase 2 (per chunk): scan, one CTA per n, 512 threads.
// Warp w reads i-rows {w, w+16, ..., w+112}; lane l covers k=4l..4l+3.
// Step t+1's G loads are issued BEFORE step t's barriers (h-independent),
// so DRAM latency overlaps the reduction -> BW-bound streaming.
// ---------------------------------------------------------------------------
__global__ __launch_bounds__(512, 1) void scan_kernel(
    const float* __restrict__ alpha,   // [R]
    const float* __restrict__ Omega,   // [R][M_OUT]
    float* __restrict__ out,           // [N][M_OUT]
    int is_first, int is_last)
{
    const int n   = blockIdx.x;
    const int tid = threadIdx.x;
    const int w   = tid >> 5;   // warp 0..15
    const int l   = tid & 31;

    __shared__ float h[128];
    __shared__ float part[16][128];

    if (tid < 128) h[tid] = is_first ? alpha[tid] : g_h[n * R + tid];
    __syncthreads();

    float4 ga[8], gb[8];

#define LOADG(dst, tl_) {                                                     \
    const float* Gt = g_G + ((size_t)(tl_)*NB + n) * ((size_t)R * R);         \
    _Pragma("unroll")                                                         \
    for (int m = 0; m < 8; ++m)                                               \
        dst[m] = *reinterpret_cast<const float4*>(                            \
            Gt + (size_t)(w + 16 * m) * R + l * 4);                           \
}

#define STEP(cur, nxt, tl_) {                                                 \
    const int tp = ((tl_) + 1 < CHUNK_T) ? (tl_) + 1 : CHUNK_T - 1;           \
    LOADG(nxt, tp);                                                           \
    float4 acc = make_float4(0.f, 0.f, 0.f, 0.f);                             \
    _Pragma("unroll")                                                         \
    for (int m = 0; m < 8; ++m) {                                             \
        const float hv = h[w + 16 * m];                                       \
        acc.x = fmaf(hv, cur[m].x, acc.x);                                    \
        acc.y = fmaf(hv, cur[m].y, acc.y);                                    \
        acc.z = fmaf(hv, cur[m].z, acc.z);                                    \
        acc.w = fmaf(hv, cur[m].w, acc.w);                                    \
    }                                                                         \
    *reinterpret_cast<float4*>(&part[w][l * 4]) = acc;                        \
    __syncthreads();                                                          \
    if (tid < 128) {                                                          \
        float s = part[0][tid];                                               \
        _Pragma("unroll")                                                     \
        for (int q = 1; q < 16; ++q) s += part[q][tid];                       \
        h[tid] = s;                                                           \
    }                                                                         \
    __syncthreads();                                                          \
}

    LOADG(ga, 0);
    for (int tl = 0; tl < CHUNK_T; tl += 2) {
        STEP(ga, gb, tl);
        STEP(gb, ga, tl + 1);
    }

#undef STEP
#undef LOADG

    if (is_last) {
        if (tid < M_OUT) {
            float s = 0.f;
            #pragma unroll 4
            for (int k = 0; k < R; ++k)
                s = fmaf(h[k], Omega[k * M_OUT + tid], s);
            out[n * M_OUT + tid] = s;
        }
    } else {
        if (tid < 128) g_h[n * R + tid] = h[tid];
    }
}

// ---------------------------------------------------------------------------
// Launch: 2 kernels per chunk, serialized on the capture stream.
// Inputs: x [N*L*D], alpha [R], A [R*D*R], Omega [R*M_OUT]; out fp32 [N,M_OUT]
// ---------------------------------------------------------------------------
extern "C" void kernel_launch(void* const* d_in, const int* in_sizes, int n_in,
                              void* d_out, int out_size)
{
    (void)in_sizes; (void)n_in; (void)out_size;
    const float* x     = (const float*)d_in[0];
    const float* alpha = (const float*)d_in[1];
    const float* A     = (const float*)d_in[2];
    const float* Omega = (const float*)d_in[3];
    float* out = (float*)d_out;

    for (int c = 0; c < NCHUNKS; ++c) {
        dim3 grid1(R, CHUNK_T);
        compute_G_kernel<<<grid1, 256>>>(x, A, c * CHUNK_T);
        scan_kernel<<<NB, 512>>>(alpha, Omega, out,
                                 c == 0 ? 1 : 0,
                                 c == NCHUNKS - 1 ? 1 : 0);
    }
}

// round 12
// speedup vs baseline: 1.6361x; 1.1427x over previous
#include <cuda_runtime.h>
#include <cstdint>

// ---------------------------------------------------------------------------
// Problem constants
// ---------------------------------------------------------------------------
constexpr int R     = 128;   // rank (i, k)
constexpr int D     = 128;   // input dim (j)
constexpr int M_OUT = 32;    // output dim
constexpr int NB    = 128;   // batch N
constexpr int L     = 512;   // sequence length

constexpr int CHUNK_T = 128;          // time chunk (keeps .bss ~1.1GB: linker-safe)
constexpr int NCHUNKS = L / CHUNK_T;  // 4
constexpr int T_PER   = 8;            // time steps per G CTA (A-slab reuse)
constexpr int JC      = 32;           // j chunk width

// Device-global scratch (sanctioned no-alloc path)
__device__ float g_G[(size_t)CHUNK_T * NB * R * R];   // G[tl][i][n][k], 1.07GB
__device__ float g_h[NB * R];                          // carried hidden state
__device__ float g_Xt[(size_t)L * NB * D];             // X transposed: [t][n][j], 32MB

// ---------------------------------------------------------------------------
// Prep: transpose x [n][t][j] -> Xt [t][n][j]  (makes G-kernel LDG coalesced)
// ---------------------------------------------------------------------------
__global__ void transpose_x_kernel(const float* __restrict__ X) {
    const size_t idx = (size_t)blockIdx.x * blockDim.x + threadIdx.x;  // float4 id
    const size_t total = (size_t)L * NB * D / 4;
    if (idx >= total) return;
    const int j4 = (int)(idx & 31);
    const int n  = (int)((idx >> 5) & 127);
    const int t  = (int)(idx >> 12);
    const float4 v = *reinterpret_cast<const float4*>(
        X + ((size_t)n * L + t) * D + j4 * 4);
    *reinterpret_cast<float4*>(
        g_Xt + ((size_t)t * NB + n) * D + j4 * 4) = v;
}

// ---------------------------------------------------------------------------
// Phase 1: G[tl][ib][n][k] = sum_j Xt[t][n][j] * A[ib][j][k]
// CTA = (ib, t-group of T_PER). A[ib] (64KB) resident in smem for all T_PER t's.
// Per t: 4 j-chunks of 32, X double-buffered, 1 bar per chunk.
// Microtile 8n x 8k per thread; k pairs = 2*tx + 32*q (FFMA2, bank-spread).
//
// XS_PITCH = 32 floats = 128B: float4 STS 16B-aligned; quarter-warp stores one
// contiguous 128B row (conflict-free); a-loads are 2-address broadcasts.
// ---------------------------------------------------------------------------
constexpr int XS_PITCH = 32;
constexpr int XS_BUF   = NB * XS_PITCH;                   // 4096 floats / buffer
constexpr int SMEM_G   = (128 * 128 + 2 * XS_BUF) * 4;    // 98,304 B (2 CTAs/SM)

__global__ __launch_bounds__(256, 2) void compute_G_kernel(
    const float* __restrict__ A,   // [R][D][R]
    int chunk_base)
{
    extern __shared__ float sm[];
    float* As = sm;                      // [j][k] 128x128
    float* Xs = sm + 128 * 128;          // [2][n][XS_PITCH]

    const int ib  = blockIdx.x;
    const int tg  = blockIdx.y;
    const int t0  = chunk_base + tg * T_PER;
    const int tid = threadIdx.x;
    const int tx  = tid & 15;            // k pairs: 2*tx + 32*q
    const int ty  = tid >> 4;            // n rows ty*8 .. +7

    // Load A slab once (coalesced LDG.128 -> STS.128, conflict-free)
    {
        const float4* src = reinterpret_cast<const float4*>(A + (size_t)ib * D * R);
        float4* dst = reinterpret_cast<float4*>(As);
        #pragma unroll
        for (int q = 0; q < 16; ++q) dst[tid + 256 * q] = src[tid + 256 * q];
    }

    alignas(16) unsigned long long c2[8][4];
    #pragma unroll
    for (int m = 0; m < 8; ++m)
        #pragma unroll
        for (int p = 0; p < 4; ++p) c2[m][p] = 0ull;

    float4 pf[4];
    // X tile for (t, jc): 128 n x 32 j. lin -> n = lin>>3, f4 = lin&7.
    auto LDGX = [&](int cc) {
        const int t  = t0 + (cc >> 2);
        const int jc = (cc & 3) * JC;
        #pragma unroll
        for (int q = 0; q < 4; ++q) {
            const int lin = tid + 256 * q;
            const int n   = lin >> 3;
            const int f4  = lin & 7;
            pf[q] = *reinterpret_cast<const float4*>(
                g_Xt + ((size_t)t * NB + n) * D + jc + f4 * 4);
        }
    };
    auto STSX = [&](int buf) {
        float* xb = Xs + buf * XS_BUF;
        #pragma unroll
        for (int q = 0; q < 4; ++q) {
            const int lin = tid + 256 * q;
            const int n   = lin >> 3;
            const int f4  = lin & 7;
            *reinterpret_cast<float4*>(xb + n * XS_PITCH + f4 * 4) = pf[q];
        }
    };

    LDGX(0);
    STSX(0);
    __syncthreads();

    for (int cc = 0; cc < T_PER * 4; ++cc) {
        const int p = cc & 1;
        if (cc + 1 < T_PER * 4) LDGX(cc + 1);     // hide LDG under compute

        const float* xb    = Xs + p * XS_BUF;
        const int    jbase = (cc & 3) * JC;
        (void)jbase;

        #pragma unroll
        for (int jj = 0; jj < JC; ++jj) {
            // a: 8 n-values at fixed j — 2-address broadcast LDS.32
            float a[8];
            #pragma unroll
            for (int m = 0; m < 8; ++m)
                a[m] = xb[(ty * 8 + m) * XS_PITCH + jj];

            // b: 4 k-pairs at stride 32 floats — 16 distinct even banks
            const unsigned long long* br =
                reinterpret_cast<const unsigned long long*>(
                    As + ((cc & 3) * JC + jj) * 128);
            unsigned long long b2[4];
            #pragma unroll
            for (int q = 0; q < 4; ++q) b2[q] = br[tx + 16 * q];

            #pragma unroll
            for (int m = 0; m < 8; ++m) {
                unsigned long long a2;
                const unsigned int au = __float_as_uint(a[m]);
                asm("mov.b64 %0, {%1, %1};" : "=l"(a2) : "r"(au));
                #pragma unroll
                for (int q = 0; q < 4; ++q)
                    asm("fma.rn.f32x2 %0, %1, %2, %0;"
                        : "+l"(c2[m][q]) : "l"(a2), "l"(b2[q]));
            }
        }

        if (cc + 1 < T_PER * 4) STSX(1 - p);      // other buffer; bar protects
        __syncthreads();

        if ((cc & 3) == 3) {                      // end of a t: write G, reset acc
            const int tl = tg * T_PER + (cc >> 2);
            float* gb = g_G + ((size_t)tl * R + ib) * ((size_t)NB * R);
            #pragma unroll
            for (int m = 0; m < 8; ++m) {
                unsigned long long* drow =
                    reinterpret_cast<unsigned long long*>(gb + (ty * 8 + m) * 128);
                #pragma unroll
                for (int q = 0; q < 4; ++q) {
                    drow[tx + 16 * q] = c2[m][q];  // STG.64, warp-contiguous
                    c2[m][q] = 0ull;
                }
            }
        }
    }
}

// ---------------------------------------------------------------------------
// Phase 2: scan (R9 version, 83.8% DRAM — unchanged). G layout [tl][i][n][k].
// ---------------------------------------------------------------------------
__global__ __launch_bounds__(512, 1) void scan_kernel(
    const float* __restrict__ alpha,
    const float* __restrict__ Omega,
    float* __restrict__ out,
    int is_first, int is_last)
{
    const int n   = blockIdx.x;
    const int tid = threadIdx.x;
    const int w   = tid >> 5;
    const int l   = tid & 31;

    __shared__ float h[128];
    __shared__ float part[16][128];

    if (tid < 128) h[tid] = is_first ? alpha[tid] : g_h[n * R + tid];
    __syncthreads();

    float4 ga[8], gb[8];

#define LOADG(dst, tl_) {                                                     \
    _Pragma("unroll")                                                         \
    for (int m = 0; m < 8; ++m)                                               \
        dst[m] = *reinterpret_cast<const float4*>(                            \
            g_G + ((size_t)(tl_) * R + (w + 16 * m)) * ((size_t)NB * R)       \
                + (size_t)n * R + l * 4);                                     \
}

#define STEP(cur, nxt, tl_) {                                                 \
    const int tp = ((tl_) + 1 < CHUNK_T) ? (tl_) + 1 : CHUNK_T - 1;           \
    LOADG(nxt, tp);                                                           \
    float4 acc = make_float4(0.f, 0.f, 0.f, 0.f);                             \
    _Pragma("unroll")                                                         \
    for (int m = 0; m < 8; ++m) {                                             \
        const float hv = h[w + 16 * m];                                       \
        acc.x = fmaf(hv, cur[m].x, acc.x);                                    \
        acc.y = fmaf(hv, cur[m].y, acc.y);                                    \
        acc.z = fmaf(hv, cur[m].z, acc.z);                                    \
        acc.w = fmaf(hv, cur[m].w, acc.w);                                    \
    }                                                                         \
    *reinterpret_cast<float4*>(&part[w][l * 4]) = acc;                        \
    __syncthreads();                                                          \
    if (tid < 128) {                                                          \
        float s = part[0][tid];                                               \
        _Pragma("unroll")                                                     \
        for (int q = 1; q < 16; ++q) s += part[q][tid];                       \
        h[tid] = s;                                                           \
    }                                                                         \
    __syncthreads();                                                          \
}

    LOADG(ga, 0);
    for (int tl = 0; tl < CHUNK_T; tl += 2) {
        STEP(ga, gb, tl);
        STEP(gb, ga, tl + 1);
    }
#undef STEP
#undef LOADG

    if (is_last) {
        if (tid < M_OUT) {
            float s = 0.f;
            #pragma unroll 4
            for (int k = 0; k < R; ++k)
                s = fmaf(h[k], Omega[k * M_OUT + tid], s);
            out[n * M_OUT + tid] = s;
        }
    } else {
        if (tid < 128) g_h[n * R + tid] = h[tid];
    }
}

// ---------------------------------------------------------------------------
// Launch. Inputs: x [N*L*D], alpha [R], A [R*D*R], Omega [R*M_OUT]; fp32 out.
// ---------------------------------------------------------------------------
extern "C" void kernel_launch(void* const* d_in, const int* in_sizes, int n_in,
                              void* d_out, int out_size)
{
    (void)in_sizes; (void)n_in; (void)out_size;
    const float* x     = (const float*)d_in[0];
    const float* alpha = (const float*)d_in[1];
    const float* A     = (const float*)d_in[2];
    const float* Omega = (const float*)d_in[3];
    float* out = (float*)d_out;

    cudaFuncSetAttribute(compute_G_kernel,
                         cudaFuncAttributeMaxDynamicSharedMemorySize, SMEM_G);

    {   // one-time X transpose (~16us)
        const size_t total4 = (size_t)L * NB * D / 4;
        transpose_x_kernel<<<(unsigned)((total4 + 255) / 256), 256>>>(x);
    }

    for (int c = 0; c < NCHUNKS; ++c) {
        dim3 grid1(R, CHUNK_T / T_PER);      // 128 ib x 16 t-groups
        compute_G_kernel<<<grid1, 256, SMEM_G>>>(A, c * CHUNK_T);
        scan_kernel<<<NB, 512>>>(alpha, Omega, out,
                                 c == 0 ? 1 : 0,
                                 c == NCHUNKS - 1 ? 1 : 0);
    }
}

// round 14
// speedup vs baseline: 1.7214x; 1.0521x over previous
#include <cuda_runtime.h>
#include <cstdint>

// ---------------------------------------------------------------------------
// Problem constants
// ---------------------------------------------------------------------------
constexpr int R     = 128;   // rank (i, k)
constexpr int D     = 128;   // input dim (j)
constexpr int M_OUT = 32;    // output dim
constexpr int NB    = 128;   // batch N
constexpr int L     = 512;   // sequence length

constexpr int CHUNK_T = 64;           // time chunk (double-buffered)
constexpr int NCHUNKS = L / CHUNK_T;  // 8
constexpr int T_PER   = 8;            // time steps per G CTA (A-slab reuse)
constexpr int JC      = 32;           // j chunk width

// Device-global scratch (sanctioned no-alloc path). Total .bss ~1.11 GB —
// safely inside the aarch64 ±4GB relocation reach.
__device__ float g_G[2][(size_t)CHUNK_T * NB * R * R];  // 2 x 512MB, ping-pong
__device__ float g_h[NB * R];                           // carried hidden state
__device__ float g_Xt[(size_t)L * NB * D];              // X transposed [t][n][j]

// ---------------------------------------------------------------------------
// Prep: transpose x [n][t][j] -> Xt [t][n][j]  (makes G-kernel LDG coalesced)
// ---------------------------------------------------------------------------
__global__ void transpose_x_kernel(const float* __restrict__ X) {
    const size_t idx = (size_t)blockIdx.x * blockDim.x + threadIdx.x;  // float4 id
    const size_t total = (size_t)L * NB * D / 4;
    if (idx >= total) return;
    const int j4 = (int)(idx & 31);
    const int n  = (int)((idx >> 5) & 127);
    const int t  = (int)(idx >> 12);
    const float4 v = *reinterpret_cast<const float4*>(
        X + ((size_t)n * L + t) * D + j4 * 4);
    *reinterpret_cast<float4*>(
        g_Xt + ((size_t)t * NB + n) * D + j4 * 4) = v;
}

// ---------------------------------------------------------------------------
// Phase 1: G[tl][ib][n][k] = sum_j Xt[t][n][j] * A[ib][j][k]
// CTA = (ib, t-group of T_PER). A[ib] (64KB) smem-resident for all T_PER t's.
//
// WARP-PRIVATE X staging: warp w computes n rows 16w..16w+15 and ALSO loads/
// stores exactly those rows of each X tile. Producer == consumer, so the
// double-buffer handoff needs only intra-warp ordering (__syncwarp), and the
// main loop has ZERO CTA barriers (one __syncthreads after the A prologue).
// ---------------------------------------------------------------------------
constexpr int XS_PITCH = 32;                              // 128B rows, 16B-aligned
constexpr int XS_BUF   = NB * XS_PITCH;                   // 4096 floats / buffer
constexpr int SMEM_G   = (128 * 128 + 2 * XS_BUF) * 4;    // 98,304 B (2 CTAs/SM)

__global__ __launch_bounds__(256, 2) void compute_G_kernel(
    const float* __restrict__ A,   // [R][D][R]
    int chunk_base, int gbuf)
{
    extern __shared__ float sm[];
    float* As = sm;                      // [j][k] 128x128
    float* Xs = sm + 128 * 128;          // [2][n][XS_PITCH]

    const int ib   = blockIdx.x;
    const int tg   = blockIdx.y;
    const int t0   = chunk_base + tg * T_PER;
    const int tid  = threadIdx.x;
    const int wid  = tid >> 5;           // warp 0..7 -> n rows 16w..16w+15
    const int lane = tid & 31;
    const int tx   = tid & 15;           // k pairs: 2*tx + 32*q
    const int ty   = tid >> 4;           // n rows ty*8 .. +7 (subset of warp's 16)

    // Load A slab once (coalesced LDG.128 -> STS.128, conflict-free)
    {
        const float4* src = reinterpret_cast<const float4*>(A + (size_t)ib * D * R);
        float4* dst = reinterpret_cast<float4*>(As);
        #pragma unroll
        for (int q = 0; q < 16; ++q) dst[tid + 256 * q] = src[tid + 256 * q];
    }

    alignas(16) unsigned long long c2[8][4];
    #pragma unroll
    for (int m = 0; m < 8; ++m)
        #pragma unroll
        for (int p = 0; p < 4; ++p) c2[m][p] = 0ull;

    // Warp-private X tile piece: 16 n-rows x 32 j. lane+32q -> n_local, f4.
    float4 pf[4];
    auto LDGX = [&](int cc) {
        const int t  = t0 + (cc >> 2);
        const int jc = (cc & 3) * JC;
        #pragma unroll
        for (int q = 0; q < 4; ++q) {
            const int lin = lane + 32 * q;           // 0..127
            const int n   = 16 * wid + (lin >> 3);   // warp's own rows
            const int f4  = lin & 7;
            pf[q] = *reinterpret_cast<const float4*>(
                g_Xt + ((size_t)t * NB + n) * D + jc + f4 * 4);
        }
    };
    auto STSX = [&](int buf) {
        float* xb = Xs + buf * XS_BUF;
        #pragma unroll
        for (int q = 0; q < 4; ++q) {
            const int lin = lane + 32 * q;
            const int n   = 16 * wid + (lin >> 3);
            const int f4  = lin & 7;
            *reinterpret_cast<float4*>(xb + n * XS_PITCH + f4 * 4) = pf[q];
        }
    };

    __syncthreads();                 // A slab visible to all warps
    LDGX(0);
    STSX(0);
    __syncwarp();

    for (int cc = 0; cc < T_PER * 4; ++cc) {
        const int p = cc & 1;
        if (cc + 1 < T_PER * 4) LDGX(cc + 1);     // hide LDG under compute

        const float* xb = Xs + p * XS_BUF;

        #pragma unroll
        for (int jj = 0; jj < JC; ++jj) {
            // a: 8 n-values at fixed j — 2-address broadcast LDS.32
            float a[8];
            #pragma unroll
            for (int m = 0; m < 8; ++m)
                a[m] = xb[(ty * 8 + m) * XS_PITCH + jj];

            // b: 4 k-pairs at stride 32 floats — 16 distinct even banks
            const unsigned long long* br =
                reinterpret_cast<const unsigned long long*>(
                    As + ((cc & 3) * JC + jj) * 128);
            unsigned long long b2[4];
            #pragma unroll
            for (int q = 0; q < 4; ++q) b2[q] = br[tx + 16 * q];

            #pragma unroll
            for (int m = 0; m < 8; ++m) {
                unsigned long long a2;
                const unsigned int au = __float_as_uint(a[m]);
                asm("mov.b64 %0, {%1, %1};" : "=l"(a2) : "r"(au));
                #pragma unroll
                for (int q = 0; q < 4; ++q)
                    asm("fma.rn.f32x2 %0, %1, %2, %0;"
                        : "+l"(c2[m][q]) : "l"(a2), "l"(b2[q]));
            }
        }

        if (cc + 1 < T_PER * 4) {
            STSX(1 - p);             // own rows; in-warp order protects buffer
            __syncwarp();
        }

        if ((cc & 3) == 3) {         // end of a t: write G, reset accumulators
            const int tl = tg * T_PER + (cc >> 2);
            float* gb = g_G[gbuf] + ((size_t)tl * R + ib) * ((size_t)NB * R);
            #pragma unroll
            for (int m = 0; m < 8; ++m) {
                unsigned long long* drow =
                    reinterpret_cast<unsigned long long*>(gb + (ty * 8 + m) * 128);
                #pragma unroll
                for (int q = 0; q < 4; ++q) {
                    drow[tx + 16 * q] = c2[m][q];  // STG.64, warp-contiguous
                    c2[m][q] = 0ull;
                }
            }
        }
    }
}

// ---------------------------------------------------------------------------
// Phase 2: scan (83.8% DRAM in R9 — structure unchanged). G[tl][i][n][k].
// Runs on a forked stream, overlapping the NEXT chunk's G computation.
// ---------------------------------------------------------------------------
__global__ __launch_bounds__(512, 1) void scan_kernel(
    const float* __restrict__ alpha,
    const float* __restrict__ Omega,
    float* __restrict__ out,
    int is_first, int is_last, int gbuf)
{
    const int n   = blockIdx.x;
    const int tid = threadIdx.x;
    const int w   = tid >> 5;
    const int l   = tid & 31;

    __shared__ float h[128];
    __shared__ float part[16][128];

    if (tid < 128) h[tid] = is_first ? alpha[tid] : g_h[n * R + tid];
    __syncthreads();

    const float* Gb = g_G[gbuf];
    float4 ga[8], gb_[8];

#define LOADG(dst, tl_) {                                                     \
    _Pragma("unroll")                                                         \
    for (int m = 0; m < 8; ++m)                                               \
        dst[m] = *reinterpret_cast<const float4*>(                            \
            Gb + ((size_t)(tl_) * R + (w + 16 * m)) * ((size_t)NB * R)        \
               + (size_t)n * R + l * 4);                                      \
}

#define STEP(cur, nxt, tl_) {                                                 \
    const int tp = ((tl_) + 1 < CHUNK_T) ? (tl_) + 1 : CHUNK_T - 1;           \
    LOADG(nxt, tp);                                                           \
    float4 acc = make_float4(0.f, 0.f, 0.f, 0.f);                             \
    _Pragma("unroll")                                                         \
    for (int m = 0; m < 8; ++m) {                                             \
        const float hv = h[w + 16 * m];                                       \
        acc.x = fmaf(hv, cur[m].x, acc.x);                                    \
        acc.y = fmaf(hv, cur[m].y, acc.y);                                    \
        acc.z = fmaf(hv, cur[m].z, acc.z);                                    \
        acc.w = fmaf(hv, cur[m].w, acc.w);                                    \
    }                                                                         \
    *reinterpret_cast<float4*>(&part[w][l * 4]) = acc;                        \
    __syncthreads();                                                          \
    if (tid < 128) {                                                          \
        float s = part[0][tid];                                               \
        _Pragma("unroll")                                                     \
        for (int q = 1; q < 16; ++q) s += part[q][tid];                       \
        h[tid] = s;                                                           \
    }                                                                         \
    __syncthreads();                                                          \
}

    LOADG(ga, 0);
    for (int tl = 0; tl < CHUNK_T; tl += 2) {
        STEP(ga, gb_, tl);
        STEP(gb_, ga, tl + 1);
    }
#undef STEP
#undef LOADG

    if (is_last) {
        if (tid < M_OUT) {
            float s = 0.f;
            #pragma unroll 4
            for (int k = 0; k < R; ++k)
                s = fmaf(h[k], Omega[k * M_OUT + tid], s);
            out[n * M_OUT + tid] = s;
        }
    } else {
        if (tid < 128) g_h[n * R + tid] = h[tid];
    }
}

// ---------------------------------------------------------------------------
// Launch. Main (capture) stream runs G chunks back-to-back; scans run on a
// forked stream against the other G buffer. Dependencies:
//   scan(c)  waits  evG[c]   (G of its chunk done)
//   G(c+2)   waits  evS[c]   (buffer c%2 free again)
//   main     waits  evS[last] (join before capture ends)
// Stream/events are created on the first (uncaptured, correctness) call only;
// every call issues the identical work DAG.
// ---------------------------------------------------------------------------
extern "C" void kernel_launch(void* const* d_in, const int* in_sizes, int n_in,
                              void* d_out, int out_size)
{
    (void)in_sizes; (void)n_in; (void)out_size;
    const float* x     = (const float*)d_in[0];
    const float* alpha = (const float*)d_in[1];
    const float* A     = (const float*)d_in[2];
    const float* Omega = (const float*)d_in[3];
    float* out = (float*)d_out;

    static cudaStream_t s2 = nullptr;
    static cudaEvent_t evG[NCHUNKS], evS[NCHUNKS];
    static bool init_done = false;
    if (!init_done) {
        cudaFuncSetAttribute(compute_G_kernel,
                             cudaFuncAttributeMaxDynamicSharedMemorySize, SMEM_G);
        cudaStreamCreateWithFlags(&s2, cudaStreamNonBlocking);
        for (int c = 0; c < NCHUNKS; ++c) {
            cudaEventCreateWithFlags(&evG[c], cudaEventDisableTiming);
            cudaEventCreateWithFlags(&evS[c], cudaEventDisableTiming);
        }
        init_done = true;
    }

    {   // one-time X transpose (~16us)
        const size_t total4 = (size_t)L * NB * D / 4;
        transpose_x_kernel<<<(unsigned)((total4 + 255) / 256), 256>>>(x);
    }

    for (int c = 0; c < NCHUNKS; ++c) {
        const int buf = c & 1;
        if (c >= 2) cudaStreamWaitEvent((cudaStream_t)0, evS[c - 2], 0);
        dim3 grid1(R, CHUNK_T / T_PER);     // 128 ib x 8 t-groups
        compute_G_kernel<<<grid1, 256, SMEM_G>>>(A, c * CHUNK_T, buf);
        cudaEventRecord(evG[c], (cudaStream_t)0);
        cudaStreamWaitEvent(s2, evG[c], 0);
        scan_kernel<<<NB, 512, 0, s2>>>(alpha, Omega, out,
                                        c == 0 ? 1 : 0,
                                        c == NCHUNKS - 1 ? 1 : 0, buf);
        cudaEventRecord(evS[c], s2);
    }
    cudaStreamWaitEvent((cudaStream_t)0, evS[NCHUNKS - 1], 0);
}

// round 15
// speedup vs baseline: 1.9238x; 1.1176x over previous
#include <cuda_runtime.h>
#include <cstdint>

// ---------------------------------------------------------------------------
// Problem constants
// ---------------------------------------------------------------------------
constexpr int R     = 128;   // rank (i, k)
constexpr int D     = 128;   // input dim (j)
constexpr int M_OUT = 32;    // output dim
constexpr int NB    = 128;   // batch N
constexpr int L     = 512;   // sequence length

constexpr int CHUNK_T = 64;           // time chunk (double-buffered)
constexpr int NCHUNKS = L / CHUNK_T;  // 8
constexpr int T_PER   = 4;            // steps per G CTA (wave-quantization fix)
constexpr int JC      = 32;           // j chunk width

// Device-global scratch (~1.11 GB total .bss — inside aarch64 reloc reach)
__device__ float g_G[2][(size_t)CHUNK_T * NB * R * R];  // 2 x 512MB ping-pong
__device__ float g_h[NB * R];                           // carried hidden state
__device__ float g_Xt[(size_t)L * NB * D];              // X transposed [t][n][j]

// ---------------------------------------------------------------------------
// Prep: transpose x [n][t][j] -> Xt [t][n][j]
// ---------------------------------------------------------------------------
__global__ void transpose_x_kernel(const float* __restrict__ X) {
    const size_t idx = (size_t)blockIdx.x * blockDim.x + threadIdx.x;
    const size_t total = (size_t)L * NB * D / 4;
    if (idx >= total) return;
    const int j4 = (int)(idx & 31);
    const int n  = (int)((idx >> 5) & 127);
    const int t  = (int)(idx >> 12);
    const float4 v = *reinterpret_cast<const float4*>(
        X + ((size_t)n * L + t) * D + j4 * 4);
    *reinterpret_cast<float4*>(
        g_Xt + ((size_t)t * NB + n) * D + j4 * 4) = v;
}

// ---------------------------------------------------------------------------
// Phase 1: G[tl][ib][n][k] = sum_j Xt[t][n][j] * A[ib][j][k]
// CTA = (ib, t-group of T_PER). A[ib] (64KB) smem-resident.
// Warp-private X staging (warp w owns n rows 16w..16w+15): no CTA barriers
// in the main loop.
//
// Xs layout: j-major [j][n] with pitch 132 words (16B-aligned rows):
//  - a-loads: 2x LDS.128 of 8 contiguous n (2 addrs/warp, 32B apart
//    -> ~1 wavefront each; was 8x 2-way-conflicted LDS.32 = 16 wf)
//  - STS: 16 scattered STS.32 (~4-way) — amortized over 32 j-steps.
// Crossbar demand drops ~128% -> ~62% of the 128B/cyc budget.
// ---------------------------------------------------------------------------
constexpr int XS_PITCH = 132;                             // words; 132%4==0
constexpr int XS_BUF   = JC * XS_PITCH;                   // 4224 floats / buffer
constexpr int SMEM_G   = (128 * 128 + 2 * XS_BUF) * 4;    // 99,328 B (2 CTA/SM)

__global__ __launch_bounds__(256, 2) void compute_G_kernel(
    const float* __restrict__ A,   // [R][D][R]
    int chunk_base, int gbuf)
{
    extern __shared__ float sm[];
    float* As = sm;                      // [j][k] 128x128
    float* Xs = sm + 128 * 128;          // [2][j=32][pitch 132]

    const int ib   = blockIdx.x;
    const int tg   = blockIdx.y;
    const int t0   = chunk_base + tg * T_PER;
    const int tid  = threadIdx.x;
    const int wid  = tid >> 5;           // warp 0..7 -> n rows 16w..16w+15
    const int lane = tid & 31;
    const int tx   = tid & 15;           // k pairs: 2*tx + 32*q
    const int ty   = tid >> 4;           // n rows ty*8 .. +7

    // Load A slab once (coalesced LDG.128 -> STS.128)
    {
        const float4* src = reinterpret_cast<const float4*>(A + (size_t)ib * D * R);
        float4* dst = reinterpret_cast<float4*>(As);
        #pragma unroll
        for (int q = 0; q < 16; ++q) dst[tid + 256 * q] = src[tid + 256 * q];
    }

    alignas(16) unsigned long long c2[8][4];
    #pragma unroll
    for (int m = 0; m < 8; ++m)
        #pragma unroll
        for (int p = 0; p < 4; ++p) c2[m][p] = 0ull;

    // Warp-private X piece: 16 n-rows x 32 j per tile.
    float4 pf[4];
    auto LDGX = [&](int cc) {
        const int t  = t0 + (cc >> 2);
        const int jc = (cc & 3) * JC;
        #pragma unroll
        for (int q = 0; q < 4; ++q) {
            const int lin = lane + 32 * q;           // 0..127
            const int n   = 16 * wid + (lin >> 3);   // warp's own rows
            const int f4  = lin & 7;                 // j-float4 index
            pf[q] = *reinterpret_cast<const float4*>(
                g_Xt + ((size_t)t * NB + n) * D + jc + f4 * 4);
        }
    };
    auto STSX = [&](int buf) {
        float* xb = Xs + buf * XS_BUF;
        #pragma unroll
        for (int q = 0; q < 4; ++q) {
            const int lin = lane + 32 * q;
            const int n   = 16 * wid + (lin >> 3);
            const int f4  = lin & 7;
            float* b = xb + (4 * f4) * XS_PITCH + n;   // j-major scatter
            b[0]            = pf[q].x;
            b[XS_PITCH]     = pf[q].y;
            b[2 * XS_PITCH] = pf[q].z;
            b[3 * XS_PITCH] = pf[q].w;
        }
    };

    __syncthreads();                 // A slab visible to all warps
    LDGX(0);
    STSX(0);
    __syncwarp();

    for (int cc = 0; cc < T_PER * 4; ++cc) {
        const int p = cc & 1;
        if (cc + 1 < T_PER * 4) LDGX(cc + 1);     // hide LDG under compute

        const float* xb = Xs + p * XS_BUF;

        #pragma unroll
        for (int jj = 0; jj < JC; ++jj) {
            // a: 8 contiguous n-floats -> 2x LDS.128 (2 addrs/warp, 1-2 wf)
            float a[8];
            const float* ar = xb + jj * XS_PITCH + ty * 8;
            *reinterpret_cast<float4*>(&a[0]) =
                *reinterpret_cast<const float4*>(ar);
            *reinterpret_cast<float4*>(&a[4]) =
                *reinterpret_cast<const float4*>(ar + 4);

            // b: 4 k-pairs at stride 32 floats — dedup'd, 1 wf each
            const unsigned long long* br =
                reinterpret_cast<const unsigned long long*>(
                    As + ((cc & 3) * JC + jj) * 128);
            unsigned long long b2[4];
            #pragma unroll
            for (int q = 0; q < 4; ++q) b2[q] = br[tx + 16 * q];

            #pragma unroll
            for (int m = 0; m < 8; ++m) {
                unsigned long long a2;
                const unsigned int au = __float_as_uint(a[m]);
                asm("mov.b64 %0, {%1, %1};" : "=l"(a2) : "r"(au));
                #pragma unroll
                for (int q = 0; q < 4; ++q)
                    asm("fma.rn.f32x2 %0, %1, %2, %0;"
                        : "+l"(c2[m][q]) : "l"(a2), "l"(b2[q]));
            }
        }

        if (cc + 1 < T_PER * 4) {
            STSX(1 - p);             // own rows; in-warp order protects buffer
            __syncwarp();
        }

        if ((cc & 3) == 3) {         // end of a t: write G, reset accumulators
            const int tl = tg * T_PER + (cc >> 2);
            float* gb = g_G[gbuf] + ((size_t)tl * R + ib) * ((size_t)NB * R);
            #pragma unroll
            for (int m = 0; m < 8; ++m) {
                unsigned long long* drow =
                    reinterpret_cast<unsigned long long*>(gb + (ty * 8 + m) * 128);
                #pragma unroll
                for (int q = 0; q < 4; ++q) {
                    drow[tx + 16 * q] = c2[m][q];  // STG.64, warp-contiguous
                    c2[m][q] = 0ull;
                }
            }
        }
    }
}

// ---------------------------------------------------------------------------
// Phase 2: scan (DRAM-bound, 84% — unchanged). Runs on forked stream,
// overlapping the next chunk's G computation. G layout [tl][i][n][k].
// ---------------------------------------------------------------------------
__global__ __launch_bounds__(512, 1) void scan_kernel(
    const float* __restrict__ alpha,
    const float* __restrict__ Omega,
    float* __restrict__ out,
    int is_first, int is_last, int gbuf)
{
    const int n   = blockIdx.x;
    const int tid = threadIdx.x;
    const int w   = tid >> 5;
    const int l   = tid & 31;

    __shared__ float h[128];
    __shared__ float part[16][128];

    if (tid < 128) h[tid] = is_first ? alpha[tid] : g_h[n * R + tid];
    __syncthreads();

    const float* Gb = g_G[gbuf];
    float4 ga[8], gb_[8];

#define LOADG(dst, tl_) {                                                     \
    _Pragma("unroll")                                                         \
    for (int m = 0; m < 8; ++m)                                               \
        dst[m] = *reinterpret_cast<const float4*>(                            \
            Gb + ((size_t)(tl_) * R + (w + 16 * m)) * ((size_t)NB * R)        \
               + (size_t)n * R + l * 4);                                      \
}

#define STEP(cur, nxt, tl_) {                                                 \
    const int tp = ((tl_) + 1 < CHUNK_T) ? (tl_) + 1 : CHUNK_T - 1;           \
    LOADG(nxt, tp);                                                           \
    float4 acc = make_float4(0.f, 0.f, 0.f, 0.f);                             \
    _Pragma("unroll")                                                         \
    for (int m = 0; m < 8; ++m) {                                             \
        const float hv = h[w + 16 * m];                                       \
        acc.x = fmaf(hv, cur[m].x, acc.x);                                    \
        acc.y = fmaf(hv, cur[m].y, acc.y);                                    \
        acc.z = fmaf(hv, cur[m].z, acc.z);                                    \
        acc.w = fmaf(hv, cur[m].w, acc.w);                                    \
    }                                                                         \
    *reinterpret_cast<float4*>(&part[w][l * 4]) = acc;                        \
    __syncthreads();                                                          \
    if (tid < 128) {                                                          \
        float s = part[0][tid];                                               \
        _Pragma("unroll")                                                     \
        for (int q = 1; q < 16; ++q) s += part[q][tid];                       \
        h[tid] = s;                                                           \
    }                                                                         \
    __syncthreads();                                                          \
}

    LOADG(ga, 0);
    for (int tl = 0; tl < CHUNK_T; tl += 2) {
        STEP(ga, gb_, tl);
        STEP(gb_, ga, tl + 1);
    }
#undef STEP
#undef LOADG

    if (is_last) {
        if (tid < M_OUT) {
            float s = 0.f;
            #pragma unroll 4
            for (int k = 0; k < R; ++k)
                s = fmaf(h[k], Omega[k * M_OUT + tid], s);
            out[n * M_OUT + tid] = s;
        }
    } else {
        if (tid < 128) g_h[n * R + tid] = h[tid];
    }
}

// ---------------------------------------------------------------------------
// Launch. Main stream: G chunks back-to-back; forked stream: scans against
// the other G buffer. scan(c) waits G(c); G(c+2) waits scan(c); join at end.
// ---------------------------------------------------------------------------
extern "C" void kernel_launch(void* const* d_in, const int* in_sizes, int n_in,
                              void* d_out, int out_size)
{
    (void)in_sizes; (void)n_in; (void)out_size;
    const float* x     = (const float*)d_in[0];
    const float* alpha = (const float*)d_in[1];
    const float* A     = (const float*)d_in[2];
    const float* Omega = (const float*)d_in[3];
    float* out = (float*)d_out;

    static cudaStream_t s2 = nullptr;
    static cudaEvent_t evG[NCHUNKS], evS[NCHUNKS];
    static bool init_done = false;
    if (!init_done) {
        cudaFuncSetAttribute(compute_G_kernel,
                             cudaFuncAttributeMaxDynamicSharedMemorySize, SMEM_G);
        cudaStreamCreateWithFlags(&s2, cudaStreamNonBlocking);
        for (int c = 0; c < NCHUNKS; ++c) {
            cudaEventCreateWithFlags(&evG[c], cudaEventDisableTiming);
            cudaEventCreateWithFlags(&evS[c], cudaEventDisableTiming);
        }
        init_done = true;
    }

    {   // one-time X transpose (~16us)
        const size_t total4 = (size_t)L * NB * D / 4;
        transpose_x_kernel<<<(unsigned)((total4 + 255) / 256), 256>>>(x);
    }

    for (int c = 0; c < NCHUNKS; ++c) {
        const int buf = c & 1;
        if (c >= 2) cudaStreamWaitEvent((cudaStream_t)0, evS[c - 2], 0);
        dim3 grid1(R, CHUNK_T / T_PER);     // 128 ib x 16 t-groups
        compute_G_kernel<<<grid1, 256, SMEM_G>>>(A, c * CHUNK_T, buf);
        cudaEventRecord(evG[c], (cudaStream_t)0);
        cudaStreamWaitEvent(s2, evG[c], 0);
        scan_kernel<<<NB, 512, 0, s2>>>(alpha, Omega, out,
                                        c == 0 ? 1 : 0,
                                        c == NCHUNKS - 1 ? 1 : 0, buf);
        cudaEventRecord(evS[c], s2);
    }
    cudaStreamWaitEvent((cudaStream_t)0, evS[NCHUNKS - 1], 0);
}